// round 2
// baseline (speedup 1.0000x reference)
#include <cuda_runtime.h>

#define BB     4
#define CC     32
#define HH     512
#define WW     512
#define NBOX   64
#define H_OUT_ 16
#define MAX_W_ 192
#define HW     (HH * WW)

// One block per (b, n, i0) with i0 in [0,8); each block computes output rows
// i0 and i0+8 for all 32 channels. 192 threads = one output column each.
// Doubling rows per thread doubles independent gather chains (MLP), and the
// 4-channel unroll batches up to 32 LDGs in flight per thread.
// Output stores use __stcs (evict-first) so the 100MB output stream does not
// evict the L2-resident image lines that the gathers re-use.
__global__ __launch_bounds__(MAX_W_) void roirotate_kernel(
    const float* __restrict__ img,      // (B, C, H, W)
    const float* __restrict__ boxes,    // (B, N, 5)
    float* __restrict__ out,            // (B, N, C, H_OUT, MAX_W)
    float* __restrict__ maskf,          // (B, N, MAX_W) as float, or null
    unsigned char* __restrict__ masku8) // (B, N, MAX_W) as u8, or null
{
    const int bi = blockIdx.x;            // 0 .. B*N*8-1
    const int i0 = bi & 7;                // row pair: i0 and i0+8
    const int bn = bi >> 3;               // b*NBOX + n
    const int b  = bn >> 6;
    const int j  = threadIdx.x;

    const float* bx = boxes + bn * 5;
    const float left = bx[0];
    const float top  = bx[1];
    const float bw   = bx[2] - left;
    const float bh   = bx[3] - top;

    // width = int32(bw/bh * H_OUT): IEEE-correct division so truncation
    // matches the JAX reference bit-exactly (mask is binary!)
    const int   width  = (int)(__fdiv_rn(bw, bh) * (float)H_OUT_);
    const float each_w = __fdiv_rn(bw, (float)(width - 1));
    const float each_h = __fdiv_rn(bh, (float)(H_OUT_ - 1));

    const bool valid = (j < width);

    // out index: ((bn*C + c)*H_OUT + i)*MAX_W + j
    const long long cstride = (long long)(H_OUT_ * MAX_W_);
    const long long obaseA = (long long)bn * CC * cstride
                           + (long long)i0 * MAX_W_ + j;
    const long long obaseB = obaseA + (long long)8 * MAX_W_;

    if (i0 == 0) {
        if (maskf)  maskf [bn * MAX_W_ + j] = valid ? 1.0f : 0.0f;
        if (masku8) masku8[bn * MAX_W_ + j] = valid ? (unsigned char)1 : (unsigned char)0;
    }

    if (!valid) {
        #pragma unroll
        for (int c = 0; c < CC; c++) {
            __stcs(&out[obaseA + (long long)c * cstride], 0.0f);
            __stcs(&out[obaseB + (long long)c * cstride], 0.0f);
        }
        return;
    }

    // ---- shared x geometry -------------------------------------------------
    const float x  = (float)j * each_w + left;
    int x0 = (int)floorf(x);
    int x1 = x0 + 1;
    x0 = max(0, min(x0, WW - 1));
    x1 = max(0, min(x1, WW - 1));
    const float wxl = (float)x1 - x;   // (x1f - x)
    const float wxr = x - (float)x0;   // (x - x0f)
    const int   dx  = x1 - x0;         // 0 or 1

    // ---- per-row y geometry ------------------------------------------------
    const float yA = (float)i0       * each_h + top;
    const float yB = (float)(i0 + 8) * each_h + top;

    int y0A = (int)floorf(yA), y1A = y0A + 1;
    y0A = max(0, min(y0A, HH - 1));  y1A = max(0, min(y1A, HH - 1));
    int y0B = (int)floorf(yB), y1B = y0B + 1;
    y0B = max(0, min(y0B, HH - 1));  y1B = max(0, min(y1B, HH - 1));

    const float wytA = (float)y1A - yA, wybA = yA - (float)y0A;
    const float wytB = (float)y1B - yB, wybB = yB - (float)y0B;

    const float waA = wxl * wytA, wbA = wxl * wybA, wcA = wxr * wytA, wdA = wxr * wybA;
    const float waB = wxl * wytB, wbB = wxl * wybB, wcB = wxr * wytB, wdB = wxr * wybB;

    const int oA = y0A * WW + x0;  const int dWA = (y1A - y0A) * WW;
    const int oB = y0B * WW + x0;  const int dWB = (y1B - y0B) * WW;

    const float* ibase = img + (long long)b * CC * HW;

    #pragma unroll 4
    for (int c = 0; c < CC; c++) {
        const float* p = ibase + c * HW;
        // row A gathers
        const float a00 = __ldg(p + oA);
        const float a01 = __ldg(p + oA + dx);
        const float a10 = __ldg(p + oA + dWA);
        const float a11 = __ldg(p + oA + dWA + dx);
        // row B gathers
        const float b00 = __ldg(p + oB);
        const float b01 = __ldg(p + oB + dx);
        const float b10 = __ldg(p + oB + dWB);
        const float b11 = __ldg(p + oB + dWB + dx);

        const float vA = a00 * waA + a10 * wbA + a01 * wcA + a11 * wdA;
        const float vB = b00 * waB + b10 * wbB + b01 * wcB + b11 * wdB;

        __stcs(&out[obaseA + (long long)c * cstride], vA);
        __stcs(&out[obaseB + (long long)c * cstride], vB);
    }
}

extern "C" void kernel_launch(void* const* d_in, const int* in_sizes, int n_in,
                              void* d_out, int out_size)
{
    const float* img   = (const float*)d_in[0];
    const float* boxes = (const float*)d_in[1];

    const long long R = (long long)BB * NBOX * CC * H_OUT_ * MAX_W_; // 25,165,824
    const long long M = (long long)BB * NBOX * MAX_W_;               // 49,152

    const dim3 grid(BB * NBOX * 8);   // 2048 blocks (2 rows per block)
    const dim3 block(MAX_W_);         // 192 threads

    if ((long long)out_size == R * 4 + M) {
        unsigned char* ob = (unsigned char*)d_out;
        roirotate_kernel<<<grid, block>>>(img, boxes, (float*)ob, nullptr, ob + R * 4);
    } else if ((long long)out_size >= R + M) {
        float* of = (float*)d_out;
        roirotate_kernel<<<grid, block>>>(img, boxes, of, of + R, nullptr);
    } else {
        float* of = (float*)d_out;
        roirotate_kernel<<<grid, block>>>(img, boxes, of, nullptr, nullptr);
    }
}

// round 3
// speedup vs baseline: 1.5169x; 1.5169x over previous
#include <cuda_runtime.h>

#define BB     4
#define CC     32
#define HH     512
#define WW     512
#define NBOX   64
#define H_OUT_ 16
#define MAX_W_ 192
#define HW     (HH * WW)
#define CHALF  16

// One block per (bn, i, channel-half). 8192 blocks of 192 threads; each block
// computes one output row (i) for 16 channels. Fine granularity maximizes
// resident-warp count and load balance (box widths vary 12..192, so narrow
// boxes make cheap blocks that interleave with wide ones).
__global__ __launch_bounds__(MAX_W_) void roirotate_kernel(
    const float* __restrict__ img,      // (B, C, H, W)
    const float* __restrict__ boxes,    // (B, N, 5)
    float* __restrict__ out,            // (B, N, C, H_OUT, MAX_W)
    float* __restrict__ maskf,          // (B, N, MAX_W) as float, or null
    unsigned char* __restrict__ masku8) // (B, N, MAX_W) as u8, or null
{
    const int bi   = blockIdx.x;          // 0 .. B*N*H_OUT*2-1
    const int half = bi & 1;              // channel half
    const int i    = (bi >> 1) & (H_OUT_ - 1);
    const int bn   = bi >> 5;             // b*NBOX + n
    const int b    = bn >> 6;
    const int j    = threadIdx.x;

    const float* bx = boxes + bn * 5;
    const float left = bx[0];
    const float top  = bx[1];
    const float bw   = bx[2] - left;
    const float bh   = bx[3] - top;

    // width = int32(bw/bh * H_OUT): IEEE-correct division so truncation
    // matches the JAX reference bit-exactly (mask is binary!)
    const int   width  = (int)(__fdiv_rn(bw, bh) * (float)H_OUT_);
    const float each_w = __fdiv_rn(bw, (float)(width - 1));
    const float each_h = __fdiv_rn(bh, (float)(H_OUT_ - 1));

    const bool valid = (j < width);

    // out index (32-bit: max 25,165,824 < 2^31):
    // ((bn*C + c)*H_OUT + i)*MAX_W + j  with c = half*CHALF + cc
    const int cstride = H_OUT_ * MAX_W_;
    const int obase   = (bn * CC + half * CHALF) * cstride + i * MAX_W_ + j;

    if (i == 0 && half == 0) {
        if (maskf)  maskf [bn * MAX_W_ + j] = valid ? 1.0f : 0.0f;
        if (masku8) masku8[bn * MAX_W_ + j] = valid ? (unsigned char)1 : (unsigned char)0;
    }

    if (!valid) {
        #pragma unroll
        for (int cc = 0; cc < CHALF; cc++)
            out[obase + cc * cstride] = 0.0f;
        return;
    }

    const float x = (float)j * each_w + left;
    const float y = (float)i * each_h + top;
    int x0 = (int)floorf(x);
    int y0 = (int)floorf(y);
    int x1 = x0 + 1;
    int y1 = y0 + 1;
    x0 = max(0, min(x0, WW - 1));
    x1 = max(0, min(x1, WW - 1));
    y0 = max(0, min(y0, HH - 1));
    y1 = max(0, min(y1, HH - 1));

    const float wxl = (float)x1 - x;
    const float wxr = x - (float)x0;
    const float wyt = (float)y1 - y;
    const float wyb = y - (float)y0;

    const float wa = wxl * wyt;
    const float wb = wxl * wyb;
    const float wc = wxr * wyt;
    const float wd = wxr * wyb;

    const int o00 = y0 * WW + x0;
    const int dx  = x1 - x0;          // 0 or 1
    const int dy  = (y1 - y0) * WW;   // 0 or WW

    const float* p = img + b * (CC * HW) + (half * CHALF) * HW + o00;

    #pragma unroll
    for (int cc = 0; cc < CHALF; cc++) {
        const float ia = __ldg(p);
        const float ic = __ldg(p + dx);
        const float ib = __ldg(p + dy);
        const float id = __ldg(p + dy + dx);
        out[obase + cc * cstride] = ia * wa + ib * wb + ic * wc + id * wd;
        p += HW;
    }
}

extern "C" void kernel_launch(void* const* d_in, const int* in_sizes, int n_in,
                              void* d_out, int out_size)
{
    const float* img   = (const float*)d_in[0];
    const float* boxes = (const float*)d_in[1];

    const long long R = (long long)BB * NBOX * CC * H_OUT_ * MAX_W_; // 25,165,824
    const long long M = (long long)BB * NBOX * MAX_W_;               // 49,152

    const dim3 grid(BB * NBOX * H_OUT_ * 2);  // 8192 blocks
    const dim3 block(MAX_W_);                 // 192 threads

    if ((long long)out_size == R * 4 + M) {
        unsigned char* ob = (unsigned char*)d_out;
        roirotate_kernel<<<grid, block>>>(img, boxes, (float*)ob, nullptr, ob + R * 4);
    } else if ((long long)out_size >= R + M) {
        float* of = (float*)d_out;
        roirotate_kernel<<<grid, block>>>(img, boxes, of, of + R, nullptr);
    } else {
        float* of = (float*)d_out;
        roirotate_kernel<<<grid, block>>>(img, boxes, of, nullptr, nullptr);
    }
}